// round 3
// baseline (speedup 1.0000x reference)
#include <cuda_runtime.h>

#define NG 5
#define NB 131072
#define NK 512
#define ND 64
#define CTA 512   // threads per CTA == rows per CTA == NK (reused for e_sq)

// Scratch for per-group loss sums (device global: no allocation allowed).
__device__ double g_loss_sum[NG];

__global__ void vq_zero_kernel() {
    if (threadIdx.x < NG) g_loss_sum[threadIdx.x] = 0.0;
}

__global__ __launch_bounds__(CTA, 1) void vq_main_kernel(
    const float* __restrict__ feat,   // [G,B,D]
    const float* __restrict__ cb,     // [G,K,D]
    float* __restrict__ out_q,        // [G,B,D]
    float* __restrict__ out_idx,      // [G,B] (as float)
    int write_q, int write_idx)
{
    extern __shared__ float sh[];
    float* sh_cb  = sh;               // NK*ND floats (128 KB)
    float* sh_esq = sh + NK * ND;     // NK floats
    float* sh_red = sh_esq + NK;      // 16 floats (warp partials)

    const int g = blockIdx.y;

    // ---- Stage this group's codebook into shared (coalesced float4) ----
    {
        float4* d4 = (float4*)sh_cb;
        const float4* s4 = (const float4*)(cb + (size_t)g * NK * ND);
        #pragma unroll
        for (int i = 0; i < (NK * ND / 4) / CTA; i++)
            d4[i * CTA + threadIdx.x] = s4[i * CTA + threadIdx.x];
    }
    __syncthreads();

    // ---- e_sq[k] = sum_d cb[k][d]^2 ----
    {
        const int k = threadIdx.x;    // CTA == NK
        const float* rowp = sh_cb + k * ND;
        float s = 0.f;
        #pragma unroll
        for (int d = 0; d < ND; d++) s = fmaf(rowp[d], rowp[d], s);
        sh_esq[k] = s;
    }
    __syncthreads();

    // ---- Load this thread's feature row into registers ----
    const int row = blockIdx.x * CTA + threadIdx.x;
    const float4* xin = (const float4*)(feat + ((size_t)g * NB + row) * ND);
    float4 x4[16];
    #pragma unroll
    for (int i = 0; i < 16; i++) x4[i] = xin[i];

    float xsq = 0.f;
    #pragma unroll
    for (int i = 0; i < 16; i++) {
        xsq = fmaf(x4[i].x, x4[i].x, xsq);
        xsq = fmaf(x4[i].y, x4[i].y, xsq);
        xsq = fmaf(x4[i].z, x4[i].z, xsq);
        xsq = fmaf(x4[i].w, x4[i].w, xsq);
    }

    // ---- Argmin over K codewords: 4 codewords / iter, broadcast LDS ----
    float best = 3.402823466e38f;
    int bestk = 0;
    #pragma unroll 1
    for (int k = 0; k < NK; k += 4) {
        const float4* r0 = (const float4*)(sh_cb + (k + 0) * ND);
        const float4* r1 = (const float4*)(sh_cb + (k + 1) * ND);
        const float4* r2 = (const float4*)(sh_cb + (k + 2) * ND);
        const float4* r3 = (const float4*)(sh_cb + (k + 3) * ND);
        float a0 = 0.f, a1 = 0.f, a2 = 0.f, a3 = 0.f;
        #pragma unroll
        for (int i = 0; i < 16; i++) {
            float4 xv = x4[i];
            float4 c0 = r0[i], c1 = r1[i], c2 = r2[i], c3 = r3[i];
            a0 = fmaf(xv.x, c0.x, a0); a1 = fmaf(xv.x, c1.x, a1);
            a2 = fmaf(xv.x, c2.x, a2); a3 = fmaf(xv.x, c3.x, a3);
            a0 = fmaf(xv.y, c0.y, a0); a1 = fmaf(xv.y, c1.y, a1);
            a2 = fmaf(xv.y, c2.y, a2); a3 = fmaf(xv.y, c3.y, a3);
            a0 = fmaf(xv.z, c0.z, a0); a1 = fmaf(xv.z, c1.z, a1);
            a2 = fmaf(xv.z, c2.z, a2); a3 = fmaf(xv.z, c3.z, a3);
            a0 = fmaf(xv.w, c0.w, a0); a1 = fmaf(xv.w, c1.w, a1);
            a2 = fmaf(xv.w, c2.w, a2); a3 = fmaf(xv.w, c3.w, a3);
        }
        // dist = (x^2 + e^2) - 2*cross  (same rounding structure as reference)
        float d0 = (xsq + sh_esq[k + 0]) - 2.0f * a0;
        float d1 = (xsq + sh_esq[k + 1]) - 2.0f * a1;
        float d2 = (xsq + sh_esq[k + 2]) - 2.0f * a2;
        float d3 = (xsq + sh_esq[k + 3]) - 2.0f * a3;
        // strict < keeps first minimum (matches jnp.argmin tie-break)
        if (d0 < best) { best = d0; bestk = k + 0; }
        if (d1 < best) { best = d1; bestk = k + 1; }
        if (d2 < best) { best = d2; bestk = k + 2; }
        if (d3 < best) { best = d3; bestk = k + 3; }
    }

    // ---- Gather codeword, write quantized_st = f + (q - f), accumulate loss ----
    const float4* qrow = (const float4*)(sh_cb + bestk * ND);
    float lsum = 0.f;
    float4* outp = (float4*)(out_q + ((size_t)g * NB + row) * ND);
    #pragma unroll
    for (int i = 0; i < 16; i++) {
        float4 qv = qrow[i];
        float4 xv = x4[i];
        float dx0 = qv.x - xv.x, dx1 = qv.y - xv.y;
        float dx2 = qv.z - xv.z, dx3 = qv.w - xv.w;
        lsum = fmaf(dx0, dx0, lsum); lsum = fmaf(dx1, dx1, lsum);
        lsum = fmaf(dx2, dx2, lsum); lsum = fmaf(dx3, dx3, lsum);
        if (write_q) {
            float4 o = make_float4(xv.x + dx0, xv.y + dx1, xv.z + dx2, xv.w + dx3);
            outp[i] = o;
        }
    }
    if (write_idx) out_idx[(size_t)g * NB + row] = (float)bestk;

    // ---- Loss reduction: warp shuffle -> shared -> double atomic per group ----
    #pragma unroll
    for (int off = 16; off > 0; off >>= 1)
        lsum += __shfl_xor_sync(0xFFFFFFFFu, lsum, off);
    if ((threadIdx.x & 31) == 0) sh_red[threadIdx.x >> 5] = lsum;
    __syncthreads();
    if (threadIdx.x == 0) {
        double s = 0.0;
        #pragma unroll
        for (int w = 0; w < CTA / 32; w++) s += (double)sh_red[w];
        atomicAdd(&g_loss_sum[g], s);
    }
}

__global__ void vq_finalize_kernel(float* __restrict__ out_loss, int write) {
    if (!write || threadIdx.x != 0 || blockIdx.x != 0) return;
    const double inv = 1.25 / ((double)NB * (double)ND);  // (1 + 0.25) * mean
    float tot = 0.f;
    #pragma unroll
    for (int g = 0; g < NG; g++) {
        float pl = (float)(g_loss_sum[g] * inv);
        out_loss[g] = pl;
        tot += pl;   // reference sums the fp32 per-group values
    }
    out_loss[NG] = tot;
}

extern "C" void kernel_launch(void* const* d_in, const int* in_sizes, int n_in,
                              void* d_out, int out_size) {
    const float* feat = (const float*)d_in[0];
    const float* cb   = (const float*)d_in[1];
    // Defensive: identify inputs by element count (features 41943040, codebooks 163840)
    if (n_in >= 2 && in_sizes[0] == NG * NK * ND) {
        const float* t = feat; feat = cb; cb = t;
    }
    float* out = (float*)d_out;

    const long long q_elems   = (long long)NG * NB * ND;              // 41943040
    const long long idx_elems = (long long)NG * NB;                   // 655360
    const long long full_sz   = q_elems + NG + 1 + idx_elems;         // 42598406
    const int write_q    = ((long long)out_size >= q_elems);
    const int write_loss = ((long long)out_size >= q_elems + NG + 1);
    const int write_idx  = ((long long)out_size >= full_sz);

    const int smem_bytes = (NK * ND + NK + 32) * (int)sizeof(float);  // ~133 KB
    cudaFuncSetAttribute(vq_main_kernel,
                         cudaFuncAttributeMaxDynamicSharedMemorySize, smem_bytes);

    vq_zero_kernel<<<1, 32>>>();

    dim3 grid(NB / CTA, NG);
    float* out_idx = out + q_elems + NG + 1;
    vq_main_kernel<<<grid, CTA, smem_bytes>>>(feat, cb, out, out_idx, write_q, write_idx);

    vq_finalize_kernel<<<1, 32>>>(out + q_elems, write_loss);
}

// round 4
// speedup vs baseline: 1.0216x; 1.0216x over previous
#include <cuda_runtime.h>
#include <float.h>

#define NG 5
#define NB 131072
#define NK 512
#define ND 64
#define CTA 512
#define XBLK (NB / CTA)          // 256
#define NCTAS (NG * XBLK)        // 1280
#define NPAIR (NK / 2)           // 256
#define PSTRIDE 66               // u64 stride per codeword-pair (64 + 2 pad)

typedef unsigned long long u64;

// Device-global scratch (no allocations allowed).
__device__ float g_part[NCTAS];
__device__ unsigned int g_done = 0;

__device__ __forceinline__ u64 ffma2(u64 a, u64 b, u64 c) {
    u64 d;
    asm("fma.rn.f32x2 %0, %1, %2, %3;" : "=l"(d) : "l"(a), "l"(b), "l"(c));
    return d;
}
__device__ __forceinline__ u64 bcast2(float f) {
    u64 r;
    asm("mov.b64 %0, {%1, %1};" : "=l"(r) : "f"(f));
    return r;
}
__device__ __forceinline__ void unpack2(u64 v, float& lo, float& hi) {
    asm("mov.b64 {%0, %1}, %2;" : "=f"(lo), "=f"(hi) : "l"(v));
}

__global__ __launch_bounds__(CTA, 1) void vq_kernel(
    const float* __restrict__ feat,   // [G,B,D]
    const float* __restrict__ cb,     // [G,K,D]
    float* __restrict__ out_q,        // [G,B,D]
    float* __restrict__ out_loss,     // [G+1]
    float* __restrict__ out_idx,      // [G,B] as float
    int write_q, int write_loss, int write_idx)
{
    extern __shared__ u64 sh[];
    u64*   sh_cbi = sh;                                 // NPAIR*PSTRIDE u64 (pair-interleaved)
    float* sh_esq = (float*)(sh + NPAIR * PSTRIDE);     // NK floats
    float* sh_red = sh_esq + NK;                        // 16 floats

    const int tid = threadIdx.x;
    const int g = blockIdx.y;

    // ---- Stage codebook pair-interleaved: u64[p*PSTRIDE + d] = (c[2p][d], c[2p+1][d]) ----
    {
        const float4* s4 = (const float4*)(cb + (size_t)g * NK * ND);
        float* base = (float*)sh_cbi;
        #pragma unroll
        for (int it = 0; it < (NK * ND / 4) / CTA; it++) {
            int i = it * CTA + tid;
            float4 v = s4[i];
            int j = i * 4;
            int k = j >> 6, d = j & 63;
            int p = k >> 1, lane = k & 1;
            int fo = (p * PSTRIDE + d) * 2 + lane;
            base[fo + 0] = v.x;
            base[fo + 2] = v.y;
            base[fo + 4] = v.z;
            base[fo + 6] = v.w;
        }
    }
    __syncthreads();

    // ---- e_sq per pair: sequential fma over d per lane (bit-identical to scalar chain) ----
    if (tid < NPAIR) {
        const u64* bp = sh_cbi + tid * PSTRIDE;
        u64 acc = 0ull;
        #pragma unroll
        for (int d = 0; d < ND; d++) acc = ffma2(bp[d], bp[d], acc);
        float e0, e1; unpack2(acc, e0, e1);
        sh_esq[2 * tid]     = e0;
        sh_esq[2 * tid + 1] = e1;
    }
    __syncthreads();

    // ---- Feature row into registers (scalar view) + xsq (sequential d order) ----
    const int row = blockIdx.x * CTA + tid;
    const float4* xin = (const float4*)(feat + ((size_t)g * NB + row) * ND);
    float xr[64];
    #pragma unroll
    for (int i = 0; i < 16; i++) {
        float4 v = xin[i];
        xr[4 * i]     = v.x;
        xr[4 * i + 1] = v.y;
        xr[4 * i + 2] = v.z;
        xr[4 * i + 3] = v.w;
    }
    float xsq = 0.f;
    #pragma unroll
    for (int j = 0; j < 64; j++) xsq = fmaf(xr[j], xr[j], xsq);

    // ---- Argmin: 4 pairs (8 codewords) per outer iter, FFMA2 dual-lane chains ----
    float best = FLT_MAX;
    int bestk = 0;
    #pragma unroll 1
    for (int p = 0; p < NPAIR; p += 4) {
        const ulonglong2* b0 = (const ulonglong2*)(sh_cbi + (size_t)(p + 0) * PSTRIDE);
        const ulonglong2* b1 = (const ulonglong2*)(sh_cbi + (size_t)(p + 1) * PSTRIDE);
        const ulonglong2* b2 = (const ulonglong2*)(sh_cbi + (size_t)(p + 2) * PSTRIDE);
        const ulonglong2* b3 = (const ulonglong2*)(sh_cbi + (size_t)(p + 3) * PSTRIDE);
        u64 a0 = 0ull, a1 = 0ull, a2 = 0ull, a3 = 0ull;
        #pragma unroll
        for (int dd = 0; dd < 32; dd++) {
            u64 xlo = bcast2(xr[2 * dd]);
            u64 xhi = bcast2(xr[2 * dd + 1]);
            ulonglong2 v0 = b0[dd];
            ulonglong2 v1 = b1[dd];
            ulonglong2 v2 = b2[dd];
            ulonglong2 v3 = b3[dd];
            a0 = ffma2(xlo, v0.x, a0);
            a1 = ffma2(xlo, v1.x, a1);
            a2 = ffma2(xlo, v2.x, a2);
            a3 = ffma2(xlo, v3.x, a3);
            a0 = ffma2(xhi, v0.y, a0);
            a1 = ffma2(xhi, v1.y, a1);
            a2 = ffma2(xhi, v2.y, a2);
            a3 = ffma2(xhi, v3.y, a3);
        }
        float c0l, c0h, c1l, c1h, c2l, c2h, c3l, c3h;
        unpack2(a0, c0l, c0h);
        unpack2(a1, c1l, c1h);
        unpack2(a2, c2l, c2h);
        unpack2(a3, c3l, c3h);
        // identical expression/rounding structure as the passing kernel
        float d0 = (xsq + sh_esq[2 * p + 0]) - 2.0f * c0l;
        float d1 = (xsq + sh_esq[2 * p + 1]) - 2.0f * c0h;
        float d2 = (xsq + sh_esq[2 * p + 2]) - 2.0f * c1l;
        float d3 = (xsq + sh_esq[2 * p + 3]) - 2.0f * c1h;
        float d4 = (xsq + sh_esq[2 * p + 4]) - 2.0f * c2l;
        float d5 = (xsq + sh_esq[2 * p + 5]) - 2.0f * c2h;
        float d6 = (xsq + sh_esq[2 * p + 6]) - 2.0f * c3l;
        float d7 = (xsq + sh_esq[2 * p + 7]) - 2.0f * c3h;
        if (d0 < best) { best = d0; bestk = 2 * p + 0; }
        if (d1 < best) { best = d1; bestk = 2 * p + 1; }
        if (d2 < best) { best = d2; bestk = 2 * p + 2; }
        if (d3 < best) { best = d3; bestk = 2 * p + 3; }
        if (d4 < best) { best = d4; bestk = 2 * p + 4; }
        if (d5 < best) { best = d5; bestk = 2 * p + 5; }
        if (d6 < best) { best = d6; bestk = 2 * p + 6; }
        if (d7 < best) { best = d7; bestk = 2 * p + 7; }
    }

    // ---- Gather codeword, quantized_st = x + (q - x), loss ----
    const u64* qp = sh_cbi + (size_t)(bestk >> 1) * PSTRIDE;
    const int lane = bestk & 1;
    float lsum = 0.f;
    float4* op4 = (float4*)(out_q + ((size_t)g * NB + row) * ND);
    #pragma unroll
    for (int i = 0; i < 16; i++) {
        float q0, q1, q2, q3, lo, hi;
        unpack2(qp[4 * i + 0], lo, hi); q0 = lane ? hi : lo;
        unpack2(qp[4 * i + 1], lo, hi); q1 = lane ? hi : lo;
        unpack2(qp[4 * i + 2], lo, hi); q2 = lane ? hi : lo;
        unpack2(qp[4 * i + 3], lo, hi); q3 = lane ? hi : lo;
        float dx0 = q0 - xr[4 * i + 0];
        float dx1 = q1 - xr[4 * i + 1];
        float dx2 = q2 - xr[4 * i + 2];
        float dx3 = q3 - xr[4 * i + 3];
        lsum = fmaf(dx0, dx0, lsum);
        lsum = fmaf(dx1, dx1, lsum);
        lsum = fmaf(dx2, dx2, lsum);
        lsum = fmaf(dx3, dx3, lsum);
        if (write_q)
            op4[i] = make_float4(xr[4 * i + 0] + dx0, xr[4 * i + 1] + dx1,
                                 xr[4 * i + 2] + dx2, xr[4 * i + 3] + dx3);
    }
    if (write_idx) out_idx[(size_t)g * NB + row] = (float)bestk;

    // ---- Loss: warp shuffle -> shared -> per-CTA partial; last CTA finalizes ----
    #pragma unroll
    for (int off = 16; off > 0; off >>= 1)
        lsum += __shfl_xor_sync(0xFFFFFFFFu, lsum, off);
    if ((tid & 31) == 0) sh_red[tid >> 5] = lsum;
    __syncthreads();
    if (tid == 0) {
        double s = 0.0;
        #pragma unroll
        for (int w = 0; w < CTA / 32; w++) s += (double)sh_red[w];
        g_part[g * XBLK + blockIdx.x] = (float)s;
        __threadfence();
        unsigned int t = atomicAdd(&g_done, 1u);
        if (t == NCTAS - 1) {
            __threadfence();
            if (write_loss) {
                const double inv = 1.25 / ((double)NB * (double)ND);  // (1+0.25)*mean
                float tot = 0.f;
                for (int g2 = 0; g2 < NG; g2++) {
                    double a = 0.0;
                    for (int b = 0; b < XBLK; b++) a += (double)g_part[g2 * XBLK + b];
                    float pl = (float)(a * inv);
                    out_loss[g2] = pl;
                    tot += pl;
                }
                out_loss[NG] = tot;
            }
            g_done = 0;  // reset for next graph replay
        }
    }
}

extern "C" void kernel_launch(void* const* d_in, const int* in_sizes, int n_in,
                              void* d_out, int out_size) {
    const float* feat = (const float*)d_in[0];
    const float* cb   = (const float*)d_in[1];
    if (n_in >= 2 && in_sizes[0] == NG * NK * ND) {  // defensive swap by size
        const float* t = feat; feat = cb; cb = t;
    }
    float* out = (float*)d_out;

    const long long q_elems   = (long long)NG * NB * ND;      // 41943040
    const long long idx_elems = (long long)NG * NB;           // 655360
    const long long full_sz   = q_elems + NG + 1 + idx_elems; // 42598406
    const int write_q    = ((long long)out_size >= q_elems);
    const int write_loss = ((long long)out_size >= q_elems + NG + 1);
    const int write_idx  = ((long long)out_size >= full_sz);

    const int smem_bytes = NPAIR * PSTRIDE * 8 + NK * 4 + 16 * 4;  // 137280 B
    cudaFuncSetAttribute(vq_kernel,
                         cudaFuncAttributeMaxDynamicSharedMemorySize, smem_bytes);

    dim3 grid(XBLK, NG);
    float* out_loss = out + q_elems;
    float* out_idx  = out + q_elems + NG + 1;
    vq_kernel<<<grid, CTA, smem_bytes>>>(feat, cb, out, out_loss, out_idx,
                                         write_q, write_loss, write_idx);
}

// round 5
// speedup vs baseline: 1.3858x; 1.3565x over previous
#include <cuda_runtime.h>
#include <float.h>

#define NG 5
#define NB 131072
#define NK 512
#define ND 64
#define CTA 256
#define RPT 2                         // rows per thread
#define ROWS_PER_CTA (CTA * RPT)      // 512
#define XBLK (NB / ROWS_PER_CTA)      // 256
#define NCTAS (NG * XBLK)             // 1280
#define NPAIR (NK / 2)                // 256
#define PSTRIDE 66                    // u64 stride per codeword-pair (64 + 2 pad)

typedef unsigned long long u64;

// Device-global scratch (no allocations allowed).
__device__ float g_part[NCTAS];
__device__ unsigned int g_done = 0;

__device__ __forceinline__ u64 ffma2(u64 a, u64 b, u64 c) {
    u64 d;
    asm("fma.rn.f32x2 %0, %1, %2, %3;" : "=l"(d) : "l"(a), "l"(b), "l"(c));
    return d;
}
__device__ __forceinline__ u64 bcast2(float f) {
    u64 r;
    asm("mov.b64 %0, {%1, %1};" : "=l"(r) : "f"(f));
    return r;
}
__device__ __forceinline__ void unpack2(u64 v, float& lo, float& hi) {
    asm("mov.b64 {%0, %1}, %2;" : "=f"(lo), "=f"(hi) : "l"(v));
}

__global__ __launch_bounds__(CTA, 1) void vq_kernel(
    const float* __restrict__ feat,   // [G,B,D]
    const float* __restrict__ cb,     // [G,K,D]
    float* __restrict__ out_q,        // [G,B,D]
    float* __restrict__ out_loss,     // [G+1]
    float* __restrict__ out_idx,      // [G,B] as float
    int write_q, int write_loss, int write_idx)
{
    extern __shared__ u64 sh[];
    u64*   sh_cbi = sh;                                 // NPAIR*PSTRIDE u64 (pair-interleaved)
    float* sh_esq = (float*)(sh + NPAIR * PSTRIDE);     // NK floats
    float* sh_red = sh_esq + NK;                        // warp partials (RPT * 8)

    const int tid = threadIdx.x;
    const int g = blockIdx.y;

    // ---- Stage codebook pair-interleaved: u64[p*PSTRIDE + d] = (c[2p][d], c[2p+1][d]) ----
    {
        const float4* s4 = (const float4*)(cb + (size_t)g * NK * ND);
        float* base = (float*)sh_cbi;
        #pragma unroll
        for (int it = 0; it < (NK * ND / 4) / CTA; it++) {
            int i = it * CTA + tid;
            float4 v = s4[i];
            int j = i * 4;
            int k = j >> 6, d = j & 63;
            int p = k >> 1, lane = k & 1;
            int fo = (p * PSTRIDE + d) * 2 + lane;
            base[fo + 0] = v.x;
            base[fo + 2] = v.y;
            base[fo + 4] = v.z;
            base[fo + 6] = v.w;
        }
    }
    __syncthreads();

    // ---- e_sq per pair (CTA == NPAIR): sequential fma per lane ----
    {
        const u64* bp = sh_cbi + tid * PSTRIDE;
        u64 acc = 0ull;
        #pragma unroll
        for (int d = 0; d < ND; d++) acc = ffma2(bp[d], bp[d], acc);
        float e0, e1; unpack2(acc, e0, e1);
        sh_esq[2 * tid]     = e0;
        sh_esq[2 * tid + 1] = e1;
    }
    __syncthreads();

    // ---- Load RPT feature rows into registers + xsq per row ----
    const int row0 = blockIdx.x * ROWS_PER_CTA + tid;   // row1 = row0 + CTA (coalesced)
    float xr0[64], xr1[64];
    {
        const float4* xin0 = (const float4*)(feat + ((size_t)g * NB + row0) * ND);
        const float4* xin1 = (const float4*)(feat + ((size_t)g * NB + row0 + CTA) * ND);
        #pragma unroll
        for (int i = 0; i < 16; i++) {
            float4 a = xin0[i];
            xr0[4 * i] = a.x; xr0[4 * i + 1] = a.y; xr0[4 * i + 2] = a.z; xr0[4 * i + 3] = a.w;
            float4 b = xin1[i];
            xr1[4 * i] = b.x; xr1[4 * i + 1] = b.y; xr1[4 * i + 2] = b.z; xr1[4 * i + 3] = b.w;
        }
    }
    float xsq0 = 0.f, xsq1 = 0.f;
    #pragma unroll
    for (int j = 0; j < 64; j++) {
        xsq0 = fmaf(xr0[j], xr0[j], xsq0);
        xsq1 = fmaf(xr1[j], xr1[j], xsq1);
    }

    // ---- Argmin: 4 pairs (8 codewords) per outer iter, shared LDS feeds both rows ----
    float best0 = FLT_MAX, best1 = FLT_MAX;
    int bk0 = 0, bk1 = 0;
    #pragma unroll 1
    for (int p = 0; p < NPAIR; p += 4) {
        const ulonglong2* b0 = (const ulonglong2*)(sh_cbi + (size_t)(p + 0) * PSTRIDE);
        const ulonglong2* b1 = (const ulonglong2*)(sh_cbi + (size_t)(p + 1) * PSTRIDE);
        const ulonglong2* b2 = (const ulonglong2*)(sh_cbi + (size_t)(p + 2) * PSTRIDE);
        const ulonglong2* b3 = (const ulonglong2*)(sh_cbi + (size_t)(p + 3) * PSTRIDE);
        u64 a00 = 0ull, a01 = 0ull, a02 = 0ull, a03 = 0ull;   // row0, pairs p..p+3
        u64 a10 = 0ull, a11 = 0ull, a12 = 0ull, a13 = 0ull;   // row1
        #pragma unroll
        for (int dd = 0; dd < 32; dd++) {
            ulonglong2 v0 = b0[dd];
            ulonglong2 v1 = b1[dd];
            ulonglong2 v2 = b2[dd];
            ulonglong2 v3 = b3[dd];
            u64 x0lo = bcast2(xr0[2 * dd]);
            u64 x0hi = bcast2(xr0[2 * dd + 1]);
            u64 x1lo = bcast2(xr1[2 * dd]);
            u64 x1hi = bcast2(xr1[2 * dd + 1]);
            a00 = ffma2(x0lo, v0.x, a00);
            a01 = ffma2(x0lo, v1.x, a01);
            a02 = ffma2(x0lo, v2.x, a02);
            a03 = ffma2(x0lo, v3.x, a03);
            a10 = ffma2(x1lo, v0.x, a10);
            a11 = ffma2(x1lo, v1.x, a11);
            a12 = ffma2(x1lo, v2.x, a12);
            a13 = ffma2(x1lo, v3.x, a13);
            a00 = ffma2(x0hi, v0.y, a00);
            a01 = ffma2(x0hi, v1.y, a01);
            a02 = ffma2(x0hi, v2.y, a02);
            a03 = ffma2(x0hi, v3.y, a03);
            a10 = ffma2(x1hi, v0.y, a10);
            a11 = ffma2(x1hi, v1.y, a11);
            a12 = ffma2(x1hi, v2.y, a12);
            a13 = ffma2(x1hi, v3.y, a13);
        }
        float e0 = sh_esq[2 * p + 0], e1 = sh_esq[2 * p + 1];
        float e2 = sh_esq[2 * p + 2], e3 = sh_esq[2 * p + 3];
        float e4 = sh_esq[2 * p + 4], e5 = sh_esq[2 * p + 5];
        float e6 = sh_esq[2 * p + 6], e7 = sh_esq[2 * p + 7];
        float cl, ch;
        // row 0
        unpack2(a00, cl, ch);
        { float d0 = (xsq0 + e0) - 2.0f * cl; float d1 = (xsq0 + e1) - 2.0f * ch;
          if (d0 < best0) { best0 = d0; bk0 = 2 * p + 0; }
          if (d1 < best0) { best0 = d1; bk0 = 2 * p + 1; } }
        unpack2(a01, cl, ch);
        { float d0 = (xsq0 + e2) - 2.0f * cl; float d1 = (xsq0 + e3) - 2.0f * ch;
          if (d0 < best0) { best0 = d0; bk0 = 2 * p + 2; }
          if (d1 < best0) { best0 = d1; bk0 = 2 * p + 3; } }
        unpack2(a02, cl, ch);
        { float d0 = (xsq0 + e4) - 2.0f * cl; float d1 = (xsq0 + e5) - 2.0f * ch;
          if (d0 < best0) { best0 = d0; bk0 = 2 * p + 4; }
          if (d1 < best0) { best0 = d1; bk0 = 2 * p + 5; } }
        unpack2(a03, cl, ch);
        { float d0 = (xsq0 + e6) - 2.0f * cl; float d1 = (xsq0 + e7) - 2.0f * ch;
          if (d0 < best0) { best0 = d0; bk0 = 2 * p + 6; }
          if (d1 < best0) { best0 = d1; bk0 = 2 * p + 7; } }
        // row 1
        unpack2(a10, cl, ch);
        { float d0 = (xsq1 + e0) - 2.0f * cl; float d1 = (xsq1 + e1) - 2.0f * ch;
          if (d0 < best1) { best1 = d0; bk1 = 2 * p + 0; }
          if (d1 < best1) { best1 = d1; bk1 = 2 * p + 1; } }
        unpack2(a11, cl, ch);
        { float d0 = (xsq1 + e2) - 2.0f * cl; float d1 = (xsq1 + e3) - 2.0f * ch;
          if (d0 < best1) { best1 = d0; bk1 = 2 * p + 2; }
          if (d1 < best1) { best1 = d1; bk1 = 2 * p + 3; } }
        unpack2(a12, cl, ch);
        { float d0 = (xsq1 + e4) - 2.0f * cl; float d1 = (xsq1 + e5) - 2.0f * ch;
          if (d0 < best1) { best1 = d0; bk1 = 2 * p + 4; }
          if (d1 < best1) { best1 = d1; bk1 = 2 * p + 5; } }
        unpack2(a13, cl, ch);
        { float d0 = (xsq1 + e6) - 2.0f * cl; float d1 = (xsq1 + e7) - 2.0f * ch;
          if (d0 < best1) { best1 = d0; bk1 = 2 * p + 6; }
          if (d1 < best1) { best1 = d1; bk1 = 2 * p + 7; } }
    }

    // ---- Gather codewords, quantized_st = x + (q - x), loss for both rows ----
    float lsum = 0.f;
    {
        const u64* qp = sh_cbi + (size_t)(bk0 >> 1) * PSTRIDE;
        const int lane = bk0 & 1;
        float4* op4 = (float4*)(out_q + ((size_t)g * NB + row0) * ND);
        #pragma unroll
        for (int i = 0; i < 16; i++) {
            float q0, q1, q2, q3, lo, hi;
            unpack2(qp[4 * i + 0], lo, hi); q0 = lane ? hi : lo;
            unpack2(qp[4 * i + 1], lo, hi); q1 = lane ? hi : lo;
            unpack2(qp[4 * i + 2], lo, hi); q2 = lane ? hi : lo;
            unpack2(qp[4 * i + 3], lo, hi); q3 = lane ? hi : lo;
            float dx0 = q0 - xr0[4 * i + 0];
            float dx1 = q1 - xr0[4 * i + 1];
            float dx2 = q2 - xr0[4 * i + 2];
            float dx3 = q3 - xr0[4 * i + 3];
            lsum = fmaf(dx0, dx0, lsum);
            lsum = fmaf(dx1, dx1, lsum);
            lsum = fmaf(dx2, dx2, lsum);
            lsum = fmaf(dx3, dx3, lsum);
            if (write_q)
                op4[i] = make_float4(xr0[4 * i + 0] + dx0, xr0[4 * i + 1] + dx1,
                                     xr0[4 * i + 2] + dx2, xr0[4 * i + 3] + dx3);
        }
    }
    {
        const u64* qp = sh_cbi + (size_t)(bk1 >> 1) * PSTRIDE;
        const int lane = bk1 & 1;
        float4* op4 = (float4*)(out_q + ((size_t)g * NB + row0 + CTA) * ND);
        #pragma unroll
        for (int i = 0; i < 16; i++) {
            float q0, q1, q2, q3, lo, hi;
            unpack2(qp[4 * i + 0], lo, hi); q0 = lane ? hi : lo;
            unpack2(qp[4 * i + 1], lo, hi); q1 = lane ? hi : lo;
            unpack2(qp[4 * i + 2], lo, hi); q2 = lane ? hi : lo;
            unpack2(qp[4 * i + 3], lo, hi); q3 = lane ? hi : lo;
            float dx0 = q0 - xr1[4 * i + 0];
            float dx1 = q1 - xr1[4 * i + 1];
            float dx2 = q2 - xr1[4 * i + 2];
            float dx3 = q3 - xr1[4 * i + 3];
            lsum = fmaf(dx0, dx0, lsum);
            lsum = fmaf(dx1, dx1, lsum);
            lsum = fmaf(dx2, dx2, lsum);
            lsum = fmaf(dx3, dx3, lsum);
            if (write_q)
                op4[i] = make_float4(xr1[4 * i + 0] + dx0, xr1[4 * i + 1] + dx1,
                                     xr1[4 * i + 2] + dx2, xr1[4 * i + 3] + dx3);
        }
    }
    if (write_idx) {
        out_idx[(size_t)g * NB + row0]       = (float)bk0;
        out_idx[(size_t)g * NB + row0 + CTA] = (float)bk1;
    }

    // ---- Loss: warp shuffle -> shared -> per-CTA partial; last CTA finalizes ----
    #pragma unroll
    for (int off = 16; off > 0; off >>= 1)
        lsum += __shfl_xor_sync(0xFFFFFFFFu, lsum, off);
    if ((tid & 31) == 0) sh_red[tid >> 5] = lsum;
    __syncthreads();
    if (tid == 0) {
        double s = 0.0;
        #pragma unroll
        for (int w = 0; w < CTA / 32; w++) s += (double)sh_red[w];
        g_part[g * XBLK + blockIdx.x] = (float)s;
        __threadfence();
        unsigned int t = atomicAdd(&g_done, 1u);
        if (t == NCTAS - 1) {
            __threadfence();
            if (write_loss) {
                const double inv = 1.25 / ((double)NB * (double)ND);  // (1+0.25)*mean
                float tot = 0.f;
                for (int g2 = 0; g2 < NG; g2++) {
                    double a = 0.0;
                    for (int b = 0; b < XBLK; b++) a += (double)g_part[g2 * XBLK + b];
                    float pl = (float)(a * inv);
                    out_loss[g2] = pl;
                    tot += pl;
                }
                out_loss[NG] = tot;
            }
            g_done = 0;  // reset for next graph replay
        }
    }
}

extern "C" void kernel_launch(void* const* d_in, const int* in_sizes, int n_in,
                              void* d_out, int out_size) {
    const float* feat = (const float*)d_in[0];
    const float* cb   = (const float*)d_in[1];
    if (n_in >= 2 && in_sizes[0] == NG * NK * ND) {  // defensive swap by size
        const float* t = feat; feat = cb; cb = t;
    }
    float* out = (float*)d_out;

    const long long q_elems   = (long long)NG * NB * ND;      // 41943040
    const long long idx_elems = (long long)NG * NB;           // 655360
    const long long full_sz   = q_elems + NG + 1 + idx_elems; // 42598406
    const int write_q    = ((long long)out_size >= q_elems);
    const int write_loss = ((long long)out_size >= q_elems + NG + 1);
    const int write_idx  = ((long long)out_size >= full_sz);

    const int smem_bytes = NPAIR * PSTRIDE * 8 + NK * 4 + 16 * 4;  // 137280 B
    cudaFuncSetAttribute(vq_kernel,
                         cudaFuncAttributeMaxDynamicSharedMemorySize, smem_bytes);

    dim3 grid(XBLK, NG);
    float* out_loss = out + q_elems;
    float* out_idx  = out + q_elems + NG + 1;
    vq_kernel<<<grid, CTA, smem_bytes>>>(feat, cb, out, out_loss, out_idx,
                                         write_q, write_loss, write_idx);
}